// round 6
// baseline (speedup 1.0000x reference)
#include <cuda_runtime.h>
#include <cstdint>

// Problem constants: S=16, P=8, N=64, D=128
#define NBLK   128
#define NROW   64
#define DIMD   128
#define STRIDE 132
#define NTHR   1024

// smem: sx[64][STRIDE], sy[64][STRIDE], nx2/rnx/ny2/rny[64]
#define SMEM_FLOATS (2 * NROW * STRIDE + 4 * NROW)

__global__ void __launch_bounds__(NTHR, 1)
vcmp_kernel(const float* __restrict__ X, const float* __restrict__ Y,
            float* __restrict__ out) {
    extern __shared__ float smem[];
    float* sx  = smem;
    float* sy  = smem + NROW * STRIDE;
    float* nx2 = sy + NROW * STRIDE;
    float* rnx = nx2 + NROW;
    float* ny2 = rnx + NROW;
    float* rny = ny2 + NROW;

    const int blk = blockIdx.x;
    const int t   = threadIdx.x;
    const int wid = t >> 5;
    const int lid = t & 31;

    // ---- Load x, y into padded smem (coalesced float4 global loads) ----
    const float4* xg = (const float4*)(X + (size_t)blk * NROW * DIMD);
    const float4* yg = (const float4*)(Y + (size_t)blk * NROW * DIMD);
#pragma unroll
    for (int k = 0; k < 2; k++) {
        int g    = k * NTHR + t;    // float4 index, 0..2047
        int row  = g >> 5;          // 32 float4 per row
        int col4 = (g & 31) * 4;
        *(float4*)(sx + row * STRIDE + col4) = xg[g];
        *(float4*)(sy + row * STRIDE + col4) = yg[g];
    }
    __syncthreads();

    // ---- Per-row squared norms + reciprocal norms (threads 0..127) ----
    if (t < 128) {
        const float* r = (t < NROW) ? (sx + t * STRIDE) : (sy + (t - NROW) * STRIDE);
        float ss = 0.f;
#pragma unroll 8
        for (int d = 0; d < DIMD; d++) ss = fmaf(r[d], r[d], ss);
        float rn = 1.0f / fmaxf(sqrtf(ss), 1e-12f);
        if (t < NROW) { nx2[t] = ss; rnx[t] = rn; }
        else          { ny2[t - NROW] = ss; rny[t - NROW] = rn; }
    }
    __syncthreads();

    // ---- Dot products via mma.sync m16n8k8 tf32 (legacy HMMA tensor path) ----
    // Gram G[n][m] = sum_d X[n][d]*Y[m][d]. 32 warps, each one 16x8 tile.
    // wid -> tile: n0 = (wid>>3)*16, m0 = (wid&7)*8. K = 128 in 16 k-steps.
    const int g_  = lid >> 2;       // group id, 0..7
    const int tg  = lid & 3;        // thread-in-group, 0..3
    const int n0  = (wid >> 3) * 16;
    const int m0  = (wid & 7) * 8;

    float c0 = 0.f, c1 = 0.f, c2 = 0.f, c3 = 0.f;
    {
        const uint32_t* pa = (const uint32_t*)(sx + (n0 + g_) * STRIDE + tg);
        const uint32_t* pb = (const uint32_t*)(sy + (m0 + g_) * STRIDE + tg);
#pragma unroll
        for (int kk = 0; kk < 16; kk++) {
            const int d0 = kk * 8;
            uint32_t a0 = pa[d0];
            uint32_t a1 = pa[8 * STRIDE + d0];
            uint32_t a2 = pa[d0 + 4];
            uint32_t a3 = pa[8 * STRIDE + d0 + 4];
            uint32_t b0 = pb[d0];
            uint32_t b1 = pb[d0 + 4];
            asm volatile(
                "mma.sync.aligned.m16n8k8.row.col.f32.tf32.tf32.f32 "
                "{%0,%1,%2,%3}, {%4,%5,%6,%7}, {%8,%9}, {%0,%1,%2,%3};"
                : "+f"(c0), "+f"(c1), "+f"(c2), "+f"(c3)
                : "r"(a0), "r"(a1), "r"(a2), "r"(a3), "r"(b0), "r"(b1));
        }
    }

    // ---- L1 loop: scalar FADD only (abs/neg fold into SASS operand mods) ----
    // n = ng*2 + i (ng = t>>5), m = mg + 32*j (mg = t&31)
    const int ng = wid;
    const int mg = lid;
    const float* xp = sx + (ng * 2) * STRIDE;
    const float* yp = sy + mg * STRIDE;

    float l1a[2][2] = {{0.f, 0.f}, {0.f, 0.f}};

#pragma unroll 2
    for (int d = 0; d < DIMD; d += 4) {
        float4 xv0 = *(const float4*)(xp + d);              // broadcast
        float4 xv1 = *(const float4*)(xp + STRIDE + d);     // broadcast
        float4 yv0 = *(const float4*)(yp + d);              // conflict-free
        float4 yv1 = *(const float4*)(yp + 32 * STRIDE + d);

        l1a[0][0] += fabsf(xv0.x - yv0.x); l1a[0][0] += fabsf(xv0.y - yv0.y);
        l1a[0][0] += fabsf(xv0.z - yv0.z); l1a[0][0] += fabsf(xv0.w - yv0.w);
        l1a[0][1] += fabsf(xv0.x - yv1.x); l1a[0][1] += fabsf(xv0.y - yv1.y);
        l1a[0][1] += fabsf(xv0.z - yv1.z); l1a[0][1] += fabsf(xv0.w - yv1.w);
        l1a[1][0] += fabsf(xv1.x - yv0.x); l1a[1][0] += fabsf(xv1.y - yv0.y);
        l1a[1][0] += fabsf(xv1.z - yv0.z); l1a[1][0] += fabsf(xv1.w - yv0.w);
        l1a[1][1] += fabsf(xv1.x - yv1.x); l1a[1][1] += fabsf(xv1.y - yv1.y);
        l1a[1][1] += fabsf(xv1.z - yv1.z); l1a[1][1] += fabsf(xv1.w - yv1.w);
    }

    // ---- Stores ----
    float* oblk = out + (size_t)blk * NROW * NROW * 3;

    // L1
#pragma unroll
    for (int i = 0; i < 2; i++) {
        const int n = ng * 2 + i;
#pragma unroll
        for (int j = 0; j < 2; j++) {
            const int m = mg + 32 * j;
            oblk[(size_t)(n * NROW + m) * 3 + 2] = l1a[i][j];
        }
    }

    // cos / l2 from the MMA C fragments
    {
        const int rn_[2] = {n0 + g_, n0 + g_ + 8};
        const int cm_[2] = {m0 + 2 * tg, m0 + 2 * tg + 1};
        const float cv[2][2] = {{c0, c1}, {c2, c3}};
#pragma unroll
        for (int i = 0; i < 2; i++) {
            const int n = rn_[i];
            const float xn2 = nx2[n];
            const float rxn = rnx[n];
#pragma unroll
            for (int j = 0; j < 2; j++) {
                const int m = cm_[j];
                const float dotv = cv[i][j];
                float l2v = sqrtf(fmaxf(xn2 + ny2[m] - 2.0f * dotv, 0.0f));
                float cosv = dotv * rxn * rny[m];
                float* o = oblk + (size_t)(n * NROW + m) * 3;
                o[0] = cosv;
                o[1] = l2v;
            }
        }
    }
}

extern "C" void kernel_launch(void* const* d_in, const int* in_sizes, int n_in,
                              void* d_out, int out_size) {
    const float* X = (const float*)d_in[0];
    const float* Y = (const float*)d_in[1];
    float* out = (float*)d_out;

    const int smem_bytes = SMEM_FLOATS * (int)sizeof(float);   // 68,608 B
    cudaFuncSetAttribute(vcmp_kernel, cudaFuncAttributeMaxDynamicSharedMemorySize,
                         smem_bytes);
    vcmp_kernel<<<NBLK, NTHR, smem_bytes>>>(X, Y, out);
}